// round 2
// baseline (speedup 1.0000x reference)
#include <cuda_runtime.h>
#include <cuda_bf16.h>
#include <math.h>

// Problem constants
#define BB 256
#define SS 512
#define KK 20
#define DD 256
#define KPAD 24   // padded row length for [d][k] transposed state arrays (96B rows, 16B aligned)

// 134 MB scratch for precomputed xW[b][s][e]  (static device global: allocation-free)
__device__ float g_xw[(size_t)BB * SS * DD];

// ---------------- packed f32x2 helpers ----------------
__device__ __forceinline__ unsigned long long f2fma(unsigned long long a,
                                                    unsigned long long b,
                                                    unsigned long long c) {
    unsigned long long d;
    asm("fma.rn.f32x2 %0, %1, %2, %3;" : "=l"(d) : "l"(a), "l"(b), "l"(c));
    return d;
}
__device__ __forceinline__ unsigned long long pk2(float a) {
    unsigned int ai = __float_as_uint(a);
    return (((unsigned long long)ai) << 32) | (unsigned long long)ai;
}
__device__ __forceinline__ void upk2(unsigned long long p, float& lo, float& hi) {
    unsigned int l = (unsigned int)(p & 0xffffffffull);
    unsigned int h = (unsigned int)(p >> 32);
    lo = __uint_as_float(l);
    hi = __uint_as_float(h);
}

// ---------------- shared memory layout (main kernel) ----------------
struct SmemMain {
    float h_T[DD][KPAD];     // h  transposed: h_T[d][k]
    float keys_T[DD][KPAD];  // keys transposed
    float kV_T[DD][KPAD];    // kV transposed (kV[k][e] stored at [e][k])
    float red[8][KK];        // per-warp reduction partials
    float sbuf[KK];          // broadcast buffer: gate g[k] / rinv[k]
    unsigned char maskb[SS];
};

// out[k] = sum_d A[d][k] * Mg[d*256 + e]     (A is smem-transposed [256][KPAD], Mg global [256][256])
// FFMA2 inner: 10 packed accumulators over k-pairs; U values ring-prefetched 2 blocks (8 rows) ahead.
__device__ __forceinline__ void mm20(const float (*A)[KPAD], const float* __restrict__ Mg,
                                     int e, float out[KK]) {
    unsigned long long acc[10];
#pragma unroll
    for (int i = 0; i < 10; i++) acc[i] = 0ull;
    float ua[4], ub[4], un[4];
#pragma unroll
    for (int j = 0; j < 4; j++) ua[j] = Mg[j * DD + e];
#pragma unroll
    for (int j = 0; j < 4; j++) ub[j] = Mg[(4 + j) * DD + e];
    for (int db = 0; db < 64; db++) {
        const int dn = db * 4 + 8;
        if (dn < DD) {
#pragma unroll
            for (int j = 0; j < 4; j++) un[j] = Mg[(dn + j) * DD + e];
        } else {
#pragma unroll
            for (int j = 0; j < 4; j++) un[j] = 0.f;
        }
#pragma unroll
        for (int dd = 0; dd < 4; dd++) {
            const int d = db * 4 + dd;
            const ulonglong2* hr = (const ulonglong2*)A[d];   // rows are 96B -> 16B aligned
            ulonglong2 p0 = hr[0], p1 = hr[1], p2 = hr[2], p3 = hr[3], p4 = hr[4];
            unsigned long long uu = pk2(ua[dd]);
            acc[0] = f2fma(p0.x, uu, acc[0]);
            acc[1] = f2fma(p0.y, uu, acc[1]);
            acc[2] = f2fma(p1.x, uu, acc[2]);
            acc[3] = f2fma(p1.y, uu, acc[3]);
            acc[4] = f2fma(p2.x, uu, acc[4]);
            acc[5] = f2fma(p2.y, uu, acc[5]);
            acc[6] = f2fma(p3.x, uu, acc[6]);
            acc[7] = f2fma(p3.y, uu, acc[7]);
            acc[8] = f2fma(p4.x, uu, acc[8]);
            acc[9] = f2fma(p4.y, uu, acc[9]);
        }
#pragma unroll
        for (int j = 0; j < 4; j++) { ua[j] = ub[j]; ub[j] = un[j]; }
    }
#pragma unroll
    for (int i = 0; i < 10; i++) upk2(acc[i], out[2 * i], out[2 * i + 1]);
}

// 20-lane-vector sum over all 256 threads; result transformed and broadcast via sm->sbuf.
// MODE 0: sigmoid, MODE 1: rsqrt(max(x, 1e-12))
template <int MODE>
__device__ __forceinline__ void reduce20(float v[KK], SmemMain* sm, int tid) {
    const int lane = tid & 31, warp = tid >> 5;
#pragma unroll
    for (int o = 16; o; o >>= 1)
#pragma unroll
        for (int k = 0; k < KK; k++) v[k] += __shfl_xor_sync(0xffffffffu, v[k], o);
    if (lane == 0) {
#pragma unroll
        for (int k = 0; k < KK; k++) sm->red[warp][k] = v[k];
    }
    __syncthreads();
    if (tid < KK) {
        float s = 0.f;
#pragma unroll
        for (int w = 0; w < 8; w++) s += sm->red[w][tid];
        sm->sbuf[tid] = (MODE == 0) ? (1.f / (1.f + expf(-s)))
                                    : rsqrtf(fmaxf(s, 1e-12f));
    }
    __syncthreads();
}

// ---------------- kernel 1: precompute xW[b][s][:] = x @ W for all (b,s) ----------------
__global__ void __launch_bounds__(256) xw_kernel(const float* __restrict__ X,
                                                 const float* __restrict__ W) {
    __shared__ float xt[DD][34];   // x tile transposed: xt[d][ss], 32 s-rows per CTA
    const int cta = blockIdx.x;                 // 4096 CTAs
    const int b = cta >> 4;
    const int s0 = (cta & 15) * 32;
    const int tid = threadIdx.x;                // e = tid

    for (int idx = tid; idx < 32 * DD; idx += 256) {
        const int ss = idx >> 8, d = idx & 255;
        xt[d][ss] = X[((size_t)(b * SS + s0 + ss)) * DD + d];
    }
    __syncthreads();

    unsigned long long acc[16];
#pragma unroll
    for (int i = 0; i < 16; i++) acc[i] = 0ull;

    float ua[4], ub[4], un[4];
#pragma unroll
    for (int j = 0; j < 4; j++) ua[j] = W[j * DD + tid];
#pragma unroll
    for (int j = 0; j < 4; j++) ub[j] = W[(4 + j) * DD + tid];
    for (int db = 0; db < 64; db++) {
        const int dn = db * 4 + 8;
        if (dn < DD) {
#pragma unroll
            for (int j = 0; j < 4; j++) un[j] = W[(dn + j) * DD + tid];
        } else {
#pragma unroll
            for (int j = 0; j < 4; j++) un[j] = 0.f;
        }
#pragma unroll
        for (int dd = 0; dd < 4; dd++) {
            const int d = db * 4 + dd;
            const unsigned long long* xr = (const unsigned long long*)xt[d];  // 136B rows, 8B aligned
            unsigned long long ww = pk2(ua[dd]);
#pragma unroll
            for (int j = 0; j < 16; j++) acc[j] = f2fma(xr[j], ww, acc[j]);
        }
#pragma unroll
        for (int j = 0; j < 4; j++) { ua[j] = ub[j]; ub[j] = un[j]; }
    }
#pragma unroll
    for (int j = 0; j < 16; j++) {
        float lo, hi;
        upk2(acc[j], lo, hi);
        g_xw[((size_t)b * SS + s0 + 2 * j) * DD + tid] = lo;
        g_xw[((size_t)b * SS + s0 + 2 * j + 1) * DD + tid] = hi;
    }
}

// ---------------- kernel 2: persistent recurrent kernel, 1 CTA per batch b ----------------
__global__ void __launch_bounds__(256, 2) rnn_kernel(const float* __restrict__ X,
                                                     const int* __restrict__ mask,
                                                     const float* __restrict__ keys,
                                                     const float* __restrict__ U,
                                                     const float* __restrict__ V,
                                                     float* __restrict__ out) {
    extern __shared__ unsigned char smraw[];
    SmemMain* sm = (SmemMain*)smraw;
    const int b = blockIdx.x;
    const int tid = threadIdx.x;   // also the column e / the dim-index d this thread owns

    // phase 0: mask row (int32 -> byte) + keys transpose
    for (int i = tid; i < SS; i += 256)
        sm->maskb[i] = (unsigned char)(mask[b * SS + i] != 0);
    const float* kb = keys + (size_t)b * KK * DD;
    for (int idx = tid; idx < KK * DD; idx += 256) {
        const int k = idx >> 8, d = idx & 255;
        sm->keys_T[d][k] = kb[idx];
    }
    __syncthreads();

    // kV[k][e] = sum_d keys[k][d] * V[d][e]; zero h
    {
        float kv[KK];
        mm20(sm->keys_T, V, tid, kv);
#pragma unroll
        for (int k = 0; k < KK; k++) {
            sm->kV_T[tid][k] = kv[k];
            sm->h_T[tid][k] = 0.f;
        }
    }
    __syncthreads();

    const float* xb = X + (size_t)b * SS * DD;
    const float* xwb = g_xw + (size_t)b * SS * DD;

    for (int s = 0; s < SS; s++) {
        if (!sm->maskb[s]) continue;   // masked step: h unchanged, skip all work

        const float x_t = xb[s * DD + tid];

        // gate pre-activation partials: v[k] = x[d] * (h[k][d] + keys[k][d]), d = tid
        float v[KK];
        {
            const float4* h4 = (const float4*)sm->h_T[tid];
            const float4* k4 = (const float4*)sm->keys_T[tid];
#pragma unroll
            for (int q = 0; q < 5; q++) {
                float4 hv = h4[q], kv = k4[q];
                v[4 * q + 0] = x_t * (hv.x + kv.x);
                v[4 * q + 1] = x_t * (hv.y + kv.y);
                v[4 * q + 2] = x_t * (hv.z + kv.z);
                v[4 * q + 3] = x_t * (hv.w + kv.w);
            }
        }
        reduce20<0>(v, sm, tid);   // sm->sbuf[k] = g[k]

        // hU GEMM: acc[k] = sum_d h[k][d] * U[d][e], e = tid
        float acc[KK];
        mm20(sm->h_T, U, tid, acc);

        const float xw = xwb[s * DD + tid];

        // update + squared-norm partials
        float upd[KK], sq[KK];
        {
            const float4* h4 = (const float4*)sm->h_T[tid];
            const float4* c4 = (const float4*)sm->kV_T[tid];
#pragma unroll
            for (int q = 0; q < 5; q++) {
                float4 hv = h4[q], cv = c4[q];
                float hvv[4] = {hv.x, hv.y, hv.z, hv.w};
                float cvv[4] = {cv.x, cv.y, cv.z, cv.w};
#pragma unroll
                for (int j = 0; j < 4; j++) {
                    const int k = 4 * q + j;
                    float t = acc[k] + cvv[j] + xw;
                    t = fmaxf(t, 0.f);                       // relu
                    float u = hvv[j] + sm->sbuf[k] * t;      // h + g * h_tilda
                    upd[k] = u;
                    sq[k] = u * u;
                }
            }
        }
        reduce20<1>(sq, sm, tid);   // sm->sbuf[k] = rsqrt(max(||upd_k||^2, 1e-12))

        // normalize + write back h
        {
            float4* h4 = (float4*)sm->h_T[tid];
#pragma unroll
            for (int q = 0; q < 5; q++) {
                float4 t;
                t.x = upd[4 * q + 0] * sm->sbuf[4 * q + 0];
                t.y = upd[4 * q + 1] * sm->sbuf[4 * q + 1];
                t.z = upd[4 * q + 2] * sm->sbuf[4 * q + 2];
                t.w = upd[4 * q + 3] * sm->sbuf[4 * q + 3];
                h4[q] = t;
            }
        }
        __syncthreads();
    }

    // emit h_T -> out[b][k][d]
#pragma unroll
    for (int k = 0; k < KK; k++)
        out[((size_t)b * KK + k) * DD + tid] = sm->h_T[tid][k];
}

extern "C" void kernel_launch(void* const* d_in, const int* in_sizes, int n_in,
                              void* d_out, int out_size) {
    const float* X = (const float*)d_in[0];                    // [B,S,D] f32
    const int* mask = (const int*)d_in[1];                     // [B,S] bool delivered as int32
    const float* keys = (const float*)d_in[2];                 // [B,K,D] f32
    const float* U = (const float*)d_in[3];                    // [D,D] f32
    const float* V = (const float*)d_in[4];                    // [D,D] f32
    const float* W = (const float*)d_in[5];                    // [D,D] f32
    float* out = (float*)d_out;                                // [B,K,D] f32

    const int smem = (int)sizeof(SmemMain);
    cudaFuncSetAttribute(rnn_kernel, cudaFuncAttributeMaxDynamicSharedMemorySize, smem);

    xw_kernel<<<BB * (SS / 32), 256>>>(X, W);
    rnn_kernel<<<BB, 256, smem>>>(X, mask, keys, U, V, out);
}

// round 3
// speedup vs baseline: 1.4017x; 1.4017x over previous
#include <cuda_runtime.h>
#include <cuda_bf16.h>
#include <math.h>

// Problem constants
#define BB 256
#define SS 512
#define KK 20
#define DD 256
#define KPAD 24   // padded row length for [d][k] transposed state arrays (96B rows, 16B aligned)

// 134 MB scratch for precomputed xW[b][s][e]  (static device global: allocation-free)
__device__ float g_xw[(size_t)BB * SS * DD];

// ---------------- packed f32x2 helpers ----------------
__device__ __forceinline__ unsigned long long f2fma(unsigned long long a,
                                                    unsigned long long b,
                                                    unsigned long long c) {
    unsigned long long d;
    asm("fma.rn.f32x2 %0, %1, %2, %3;" : "=l"(d) : "l"(a), "l"(b), "l"(c));
    return d;
}
__device__ __forceinline__ unsigned long long pk2(float a) {
    unsigned int ai = __float_as_uint(a);
    return (((unsigned long long)ai) << 32) | (unsigned long long)ai;
}
__device__ __forceinline__ void upk2(unsigned long long p, float& lo, float& hi) {
    unsigned int l = (unsigned int)(p & 0xffffffffull);
    unsigned int h = (unsigned int)(p >> 32);
    lo = __uint_as_float(l);
    hi = __uint_as_float(h);
}

// ---------------- shared memory layout (main kernel) ----------------
struct SmemMain {
    float h_T[DD][KPAD];     // h  transposed: h_T[d][k]
    float keys_T[DD][KPAD];  // keys transposed
    float kV_T[DD][KPAD];    // kV transposed (kV[k][e] stored at [e][k])
    float accT[KK * DD];     // GEMM staging: accT[k*256 + e]  (float2 per col pair)
    float red[8][KK];        // per-warp reduction partials
    float sbuf[KK];          // broadcast buffer: gate g[k] / rinv[k]
    unsigned char maskb[SS];
};

// out[k] = sum_d A[d][k] * Mg[d*256 + e]   (init/kV path; full d range, 1 column per thread)
__device__ __forceinline__ void mm20(const float (*A)[KPAD], const float* __restrict__ Mg,
                                     int e, float out[KK]) {
    unsigned long long acc[10];
#pragma unroll
    for (int i = 0; i < 10; i++) acc[i] = 0ull;
    float ua[4], ub[4], un[4];
#pragma unroll
    for (int j = 0; j < 4; j++) ua[j] = Mg[j * DD + e];
#pragma unroll
    for (int j = 0; j < 4; j++) ub[j] = Mg[(4 + j) * DD + e];
    for (int db = 0; db < 64; db++) {
        const int dn = db * 4 + 8;
        if (dn < DD) {
#pragma unroll
            for (int j = 0; j < 4; j++) un[j] = Mg[(dn + j) * DD + e];
        } else {
#pragma unroll
            for (int j = 0; j < 4; j++) un[j] = 0.f;
        }
#pragma unroll
        for (int dd = 0; dd < 4; dd++) {
            const int d = db * 4 + dd;
            const ulonglong2* hr = (const ulonglong2*)A[d];
            ulonglong2 p0 = hr[0], p1 = hr[1], p2 = hr[2], p3 = hr[3], p4 = hr[4];
            unsigned long long uu = pk2(ua[dd]);
            acc[0] = f2fma(p0.x, uu, acc[0]);
            acc[1] = f2fma(p0.y, uu, acc[1]);
            acc[2] = f2fma(p1.x, uu, acc[2]);
            acc[3] = f2fma(p1.y, uu, acc[3]);
            acc[4] = f2fma(p2.x, uu, acc[4]);
            acc[5] = f2fma(p2.y, uu, acc[5]);
            acc[6] = f2fma(p3.x, uu, acc[6]);
            acc[7] = f2fma(p3.y, uu, acc[7]);
            acc[8] = f2fma(p4.x, uu, acc[8]);
            acc[9] = f2fma(p4.y, uu, acc[9]);
        }
#pragma unroll
        for (int j = 0; j < 4; j++) { ua[j] = ub[j]; ub[j] = un[j]; }
    }
#pragma unroll
    for (int i = 0; i < 10; i++) upk2(acc[i], out[2 * i], out[2 * i + 1]);
}

// 20-lane-vector sum over all 256 threads; result transformed and broadcast via sm->sbuf.
// MODE 0: sigmoid, MODE 1: rsqrt(max(x, 1e-12))
template <int MODE>
__device__ __forceinline__ void reduce20(float v[KK], SmemMain* sm, int tid) {
    const int lane = tid & 31, warp = tid >> 5;
#pragma unroll
    for (int o = 16; o; o >>= 1)
#pragma unroll
        for (int k = 0; k < KK; k++) v[k] += __shfl_xor_sync(0xffffffffu, v[k], o);
    if (lane == 0) {
#pragma unroll
        for (int k = 0; k < KK; k++) sm->red[warp][k] = v[k];
    }
    __syncthreads();
    if (tid < KK) {
        float s = 0.f;
#pragma unroll
        for (int w = 0; w < 8; w++) s += sm->red[w][tid];
        sm->sbuf[tid] = (MODE == 0) ? (1.f / (1.f + expf(-s)))
                                    : rsqrtf(fmaxf(s, 1e-12f));
    }
    __syncthreads();
}

// ---------------- kernel 1: precompute xW[b][s][:] = x @ W for all (b,s) ----------------
__global__ void __launch_bounds__(256) xw_kernel(const float* __restrict__ X,
                                                 const float* __restrict__ W) {
    __shared__ float xt[DD][34];   // x tile transposed: xt[d][ss], 32 s-rows per CTA
    const int cta = blockIdx.x;                 // 4096 CTAs
    const int b = cta >> 4;
    const int s0 = (cta & 15) * 32;
    const int tid = threadIdx.x;                // e = tid

    for (int idx = tid; idx < 32 * DD; idx += 256) {
        const int ss = idx >> 8, d = idx & 255;
        xt[d][ss] = X[((size_t)(b * SS + s0 + ss)) * DD + d];
    }
    __syncthreads();

    unsigned long long acc[16];
#pragma unroll
    for (int i = 0; i < 16; i++) acc[i] = 0ull;

    float ua[4], ub[4], un[4];
#pragma unroll
    for (int j = 0; j < 4; j++) ua[j] = W[j * DD + tid];
#pragma unroll
    for (int j = 0; j < 4; j++) ub[j] = W[(4 + j) * DD + tid];
    for (int db = 0; db < 64; db++) {
        const int dn = db * 4 + 8;
        if (dn < DD) {
#pragma unroll
            for (int j = 0; j < 4; j++) un[j] = W[(dn + j) * DD + tid];
        } else {
#pragma unroll
            for (int j = 0; j < 4; j++) un[j] = 0.f;
        }
#pragma unroll
        for (int dd = 0; dd < 4; dd++) {
            const int d = db * 4 + dd;
            const unsigned long long* xr = (const unsigned long long*)xt[d];
            unsigned long long ww = pk2(ua[dd]);
#pragma unroll
            for (int j = 0; j < 16; j++) acc[j] = f2fma(xr[j], ww, acc[j]);
        }
#pragma unroll
        for (int j = 0; j < 4; j++) { ua[j] = ub[j]; ub[j] = un[j]; }
    }
#pragma unroll
    for (int j = 0; j < 16; j++) {
        float lo, hi;
        upk2(acc[j], lo, hi);
        g_xw[((size_t)b * SS + s0 + 2 * j) * DD + tid] = lo;
        g_xw[((size_t)b * SS + s0 + 2 * j + 1) * DD + tid] = hi;
    }
}

// ---------------- kernel 2: persistent recurrent kernel, 1 CTA per batch b ----------------
__global__ void __launch_bounds__(256, 2) rnn_kernel(const float* __restrict__ X,
                                                     const int* __restrict__ mask,
                                                     const float* __restrict__ keys,
                                                     const float* __restrict__ U,
                                                     const float* __restrict__ V,
                                                     float* __restrict__ out) {
    extern __shared__ unsigned char smraw[];
    SmemMain* sm = (SmemMain*)smraw;
    const int b = blockIdx.x;
    const int tid = threadIdx.x;   // column e (gate/update phases); (half,col) in GEMM phase

    // phase 0: mask row (int32 -> byte) + keys transpose
    for (int i = tid; i < SS; i += 256)
        sm->maskb[i] = (unsigned char)(mask[b * SS + i] != 0);
    const float* kb = keys + (size_t)b * KK * DD;
    for (int idx = tid; idx < KK * DD; idx += 256) {
        const int k = idx >> 8, d = idx & 255;
        sm->keys_T[d][k] = kb[idx];
    }
    __syncthreads();

    // kV[k][e] = sum_d keys[k][d] * V[d][e]; zero h
    {
        float kv[KK];
        mm20(sm->keys_T, V, tid, kv);
#pragma unroll
        for (int k = 0; k < KK; k++) {
            sm->kV_T[tid][k] = kv[k];
            sm->h_T[tid][k] = 0.f;
        }
    }
    __syncthreads();

    const float* xb = X + (size_t)b * SS * DD;
    const float* xwb = g_xw + (size_t)b * SS * DD;

    const int half = tid >> 7;            // 0 or 1 -> d-range
    const int col = tid & 127;            // e-pair (2col, 2col+1)
    const int d0 = half * 128;
    const float2* Up = (const float2*)U + col;   // row d -> Up[d*128]
    float2* accT2 = (float2*)sm->accT + col;     // accT[k*256 + 2col..2col+1]

    for (int s = 0; s < SS; s++) {
        if (!sm->maskb[s]) continue;   // masked step: h unchanged, skip all work

        const float x_t = xb[s * DD + tid];

        // gate pre-activation partials: v[k] = x[d] * (h[k][d] + keys[k][d]), d = tid
        float v[KK];
        {
            const float4* h4 = (const float4*)sm->h_T[tid];
            const float4* k4 = (const float4*)sm->keys_T[tid];
#pragma unroll
            for (int q = 0; q < 5; q++) {
                float4 hv = h4[q], kv = k4[q];
                v[4 * q + 0] = x_t * (hv.x + kv.x);
                v[4 * q + 1] = x_t * (hv.y + kv.y);
                v[4 * q + 2] = x_t * (hv.z + kv.z);
                v[4 * q + 3] = x_t * (hv.w + kv.w);
            }
        }
        reduce20<0>(v, sm, tid);   // sm->sbuf[k] = g[k]

        // ---- hU GEMM, e-pair x d-half blocked ----
        // thread (half,col): partial[k][e0,e1] = sum_{d in [d0,d0+128)} h[k][d] * U[d][e]
        {
            unsigned long long a0[10], a1[10];   // pairs over k, for e0 and e1
#pragma unroll
            for (int i = 0; i < 10; i++) { a0[i] = 0ull; a1[i] = 0ull; }

            float2 ua[4], ub[4], un[4];
#pragma unroll
            for (int j = 0; j < 4; j++) ua[j] = Up[(d0 + j) * 128];
#pragma unroll
            for (int j = 0; j < 4; j++) ub[j] = Up[(d0 + 4 + j) * 128];
            for (int db = 0; db < 32; db++) {
                const int dnb = db * 4 + 8;
                if (dnb < 128) {
#pragma unroll
                    for (int j = 0; j < 4; j++) un[j] = Up[(d0 + dnb + j) * 128];
                } else {
#pragma unroll
                    for (int j = 0; j < 4; j++) un[j] = make_float2(0.f, 0.f);
                }
#pragma unroll
                for (int dd = 0; dd < 4; dd++) {
                    const int d = d0 + db * 4 + dd;
                    const ulonglong2* hr = (const ulonglong2*)sm->h_T[d];
                    ulonglong2 p0 = hr[0], p1 = hr[1], p2 = hr[2], p3 = hr[3], p4 = hr[4];
                    unsigned long long u0 = pk2(ua[dd].x);
                    unsigned long long u1 = pk2(ua[dd].y);
                    a0[0] = f2fma(p0.x, u0, a0[0]);  a1[0] = f2fma(p0.x, u1, a1[0]);
                    a0[1] = f2fma(p0.y, u0, a0[1]);  a1[1] = f2fma(p0.y, u1, a1[1]);
                    a0[2] = f2fma(p1.x, u0, a0[2]);  a1[2] = f2fma(p1.x, u1, a1[2]);
                    a0[3] = f2fma(p1.y, u0, a0[3]);  a1[3] = f2fma(p1.y, u1, a1[3]);
                    a0[4] = f2fma(p2.x, u0, a0[4]);  a1[4] = f2fma(p2.x, u1, a1[4]);
                    a0[5] = f2fma(p2.y, u0, a0[5]);  a1[5] = f2fma(p2.y, u1, a1[5]);
                    a0[6] = f2fma(p3.x, u0, a0[6]);  a1[6] = f2fma(p3.x, u1, a1[6]);
                    a0[7] = f2fma(p3.y, u0, a0[7]);  a1[7] = f2fma(p3.y, u1, a1[7]);
                    a0[8] = f2fma(p4.x, u0, a0[8]);  a1[8] = f2fma(p4.x, u1, a1[8]);
                    a0[9] = f2fma(p4.y, u0, a0[9]);  a1[9] = f2fma(p4.y, u1, a1[9]);
                }
#pragma unroll
                for (int j = 0; j < 4; j++) { ua[j] = ub[j]; ub[j] = un[j]; }
            }

            float o0[KK], o1[KK];
#pragma unroll
            for (int i = 0; i < 10; i++) {
                upk2(a0[i], o0[2 * i], o0[2 * i + 1]);
                upk2(a1[i], o1[2 * i], o1[2 * i + 1]);
            }
            // half 0 writes partials; half 1 folds its partials in after a barrier
            if (half == 0) {
#pragma unroll
                for (int k = 0; k < KK; k++)
                    accT2[k * 128] = make_float2(o0[k], o1[k]);
            }
            __syncthreads();
            if (half == 1) {
#pragma unroll
                for (int k = 0; k < KK; k++) {
                    float2 t = accT2[k * 128];
                    t.x += o0[k];
                    t.y += o1[k];
                    accT2[k * 128] = t;
                }
            }
            __syncthreads();
        }

        // acc[k] for this thread's column e = tid (coalesced LDS.32 reads)
        float acc[KK];
#pragma unroll
        for (int k = 0; k < KK; k++) acc[k] = sm->accT[k * DD + tid];

        const float xw = xwb[s * DD + tid];

        // update + squared-norm partials
        float upd[KK], sq[KK];
        {
            const float4* h4 = (const float4*)sm->h_T[tid];
            const float4* c4 = (const float4*)sm->kV_T[tid];
#pragma unroll
            for (int q = 0; q < 5; q++) {
                float4 hv = h4[q], cv = c4[q];
                float hvv[4] = {hv.x, hv.y, hv.z, hv.w};
                float cvv[4] = {cv.x, cv.y, cv.z, cv.w};
#pragma unroll
                for (int j = 0; j < 4; j++) {
                    const int k = 4 * q + j;
                    float t = acc[k] + cvv[j] + xw;
                    t = fmaxf(t, 0.f);                       // relu
                    float u = hvv[j] + sm->sbuf[k] * t;      // h + g * h_tilda
                    upd[k] = u;
                    sq[k] = u * u;
                }
            }
        }
        reduce20<1>(sq, sm, tid);   // sm->sbuf[k] = rsqrt(max(||upd_k||^2, 1e-12))

        // normalize + write back h
        {
            float4* h4 = (float4*)sm->h_T[tid];
#pragma unroll
            for (int q = 0; q < 5; q++) {
                float4 t;
                t.x = upd[4 * q + 0] * sm->sbuf[4 * q + 0];
                t.y = upd[4 * q + 1] * sm->sbuf[4 * q + 1];
                t.z = upd[4 * q + 2] * sm->sbuf[4 * q + 2];
                t.w = upd[4 * q + 3] * sm->sbuf[4 * q + 3];
                h4[q] = t;
            }
        }
        __syncthreads();
    }

    // emit h_T -> out[b][k][d]
#pragma unroll
    for (int k = 0; k < KK; k++)
        out[((size_t)b * KK + k) * DD + tid] = sm->h_T[tid][k];
}

extern "C" void kernel_launch(void* const* d_in, const int* in_sizes, int n_in,
                              void* d_out, int out_size) {
    const float* X = (const float*)d_in[0];                    // [B,S,D] f32
    const int* mask = (const int*)d_in[1];                     // [B,S] bool delivered as int32
    const float* keys = (const float*)d_in[2];                 // [B,K,D] f32
    const float* U = (const float*)d_in[3];                    // [D,D] f32
    const float* V = (const float*)d_in[4];                    // [D,D] f32
    const float* W = (const float*)d_in[5];                    // [D,D] f32
    float* out = (float*)d_out;                                // [B,K,D] f32

    const int smem = (int)sizeof(SmemMain);
    cudaFuncSetAttribute(rnn_kernel, cudaFuncAttributeMaxDynamicSharedMemorySize, smem);

    xw_kernel<<<BB * (SS / 32), 256>>>(X, W);
    rnn_kernel<<<BB, 256, smem>>>(X, mask, keys, U, V, out);
}